// round 4
// baseline (speedup 1.0000x reference)
#include <cuda_runtime.h>
#include <cuda_bf16.h>

#define EPSF 1e-12f
#define NEGF -1e30f

// ---------------- static scratch (no runtime allocation allowed) ----------------
// cap_n: 128*60 = 7680 rows x 1024   img_n: 128*36 = 4608 rows x 1024
// sim:   7680 x 4608 (leaky-relu applied)
__device__ float g_cap_n[7680 * 1024];
__device__ float g_img_n[4608 * 1024];
__device__ float g_sim[7680 * 4608];

// ---------------- packed f32x2 helpers (sm_103a full-rate fp32 path) ----------------
__device__ __forceinline__ void fma_x2(unsigned long long &d, unsigned long long a, unsigned long long b) {
    asm("fma.rn.f32x2 %0, %1, %2, %0;" : "+l"(d) : "l"(a), "l"(b));
}
__device__ __forceinline__ unsigned long long dup_f(float x) {
    unsigned long long r;
    asm("mov.b64 %0, {%1, %1};" : "=l"(r) : "f"(x));
    return r;
}

// ---------------- kernel 1: L2 normalize rows of 1024 ----------------
__global__ __launch_bounds__(256) void nrm_kernel(const float* __restrict__ img,
                                                  const float* __restrict__ cap) {
    int row = blockIdx.x;
    const float4* src;
    float4* dst;
    if (row < 7680) {
        src = (const float4*)(cap + (size_t)row * 1024);
        dst = (float4*)(g_cap_n + (size_t)row * 1024);
    } else {
        int r = row - 7680;
        src = (const float4*)(img + (size_t)r * 1024);
        dst = (float4*)(g_img_n + (size_t)r * 1024);
    }
    int t = threadIdx.x;                 // 256 threads, 1024/4 = 256 float4
    float4 v = src[t];
    float ss = v.x * v.x + v.y * v.y + v.z * v.z + v.w * v.w;
#pragma unroll
    for (int o = 16; o > 0; o >>= 1) ss += __shfl_xor_sync(0xffffffffu, ss, o);
    __shared__ float red[8];
    if ((t & 31) == 0) red[t >> 5] = ss;
    __syncthreads();
    float tot = red[0] + red[1] + red[2] + red[3] + red[4] + red[5] + red[6] + red[7];
    float inv = 1.0f / fmaxf(sqrtf(tot), EPSF);
    v.x *= inv; v.y *= inv; v.z *= inv; v.w *= inv;
    dst[t] = v;
}

// ---------------- kernel 2: sim GEMM 7680 x 4608 x 1024 (f32x2 accumulators) ----------------
// C[cw][ir] = dot(cap_n[cw], img_n[ir]); leaky-relu fused in epilogue.
// Tile 128x128, BK=16. 256 threads, 8x8 per thread as 4 row-pairs x 8 cols.
__global__ __launch_bounds__(256, 2) void gemm_kernel() {
    __shared__ float As[16][132];   // [k][m], pad 132 keeps 16B alignment + spreads banks
    __shared__ float Bs[16][132];   // [k][n]
    const int tid = threadIdx.x;
    const int bx = blockIdx.x;      // 0..35  (img / N tiles)
    const int by = blockIdx.y;      // 0..59  (cap / M tiles)
    const float* A = g_cap_n + (size_t)by * 128 * 1024;
    const float* B = g_img_n + (size_t)bx * 128 * 1024;
    const int lrow = tid >> 2;          // 0..63
    const int lk   = (tid & 3) * 4;     // 0,4,8,12
    const int tx = tid & 15;
    const int ty = tid >> 4;

    unsigned long long acc[4][8];
#pragma unroll
    for (int p = 0; p < 4; p++)
#pragma unroll
        for (int j = 0; j < 8; j++) acc[p][j] = 0ULL;

#pragma unroll 1
    for (int kt = 0; kt < 1024; kt += 16) {
        // global fetch for this tile (before sync: overlaps previous compute)
        float4 a0 = *(const float4*)(A + (size_t)lrow * 1024 + kt + lk);
        float4 a1 = *(const float4*)(A + (size_t)(lrow + 64) * 1024 + kt + lk);
        float4 b0 = *(const float4*)(B + (size_t)lrow * 1024 + kt + lk);
        float4 b1 = *(const float4*)(B + (size_t)(lrow + 64) * 1024 + kt + lk);
        __syncthreads();
        As[lk + 0][lrow] = a0.x; As[lk + 1][lrow] = a0.y; As[lk + 2][lrow] = a0.z; As[lk + 3][lrow] = a0.w;
        As[lk + 0][lrow + 64] = a1.x; As[lk + 1][lrow + 64] = a1.y; As[lk + 2][lrow + 64] = a1.z; As[lk + 3][lrow + 64] = a1.w;
        Bs[lk + 0][lrow] = b0.x; Bs[lk + 1][lrow] = b0.y; Bs[lk + 2][lrow] = b0.z; Bs[lk + 3][lrow] = b0.w;
        Bs[lk + 0][lrow + 64] = b1.x; Bs[lk + 1][lrow + 64] = b1.y; Bs[lk + 2][lrow + 64] = b1.z; Bs[lk + 3][lrow + 64] = b1.w;
        __syncthreads();
#pragma unroll
        for (int k = 0; k < 16; k++) {
            // A row-pairs come pre-packed from a 16B shared load
            ulonglong2 apl = *reinterpret_cast<const ulonglong2*>(&As[k][ty * 8]);
            ulonglong2 aph = *reinterpret_cast<const ulonglong2*>(&As[k][ty * 8 + 4]);
            float4 bv0 = *reinterpret_cast<const float4*>(&Bs[k][tx * 8]);
            float4 bv1 = *reinterpret_cast<const float4*>(&Bs[k][tx * 8 + 4]);
            unsigned long long ap0 = apl.x, ap1 = apl.y, ap2 = aph.x, ap3 = aph.y;
            unsigned long long bd[8];
            bd[0] = dup_f(bv0.x); bd[1] = dup_f(bv0.y); bd[2] = dup_f(bv0.z); bd[3] = dup_f(bv0.w);
            bd[4] = dup_f(bv1.x); bd[5] = dup_f(bv1.y); bd[6] = dup_f(bv1.z); bd[7] = dup_f(bv1.w);
#pragma unroll
            for (int j = 0; j < 8; j++) {
                fma_x2(acc[0][j], ap0, bd[j]);
                fma_x2(acc[1][j], ap1, bd[j]);
                fma_x2(acc[2][j], ap2, bd[j]);
                fma_x2(acc[3][j], ap3, bd[j]);
            }
        }
    }
    // epilogue: leaky relu + store
    const int colbase = bx * 128 + tx * 8;
#pragma unroll
    for (int p = 0; p < 4; p++) {
        float vlo[8], vhi[8];
#pragma unroll
        for (int j = 0; j < 8; j++) {
            float2 f = *reinterpret_cast<float2*>(&acc[p][j]);
            vlo[j] = (f.x >= 0.f) ? f.x : 0.1f * f.x;
            vhi[j] = (f.y >= 0.f) ? f.y : 0.1f * f.y;
        }
        int row0 = by * 128 + ty * 8 + 2 * p;
        float4* d0 = reinterpret_cast<float4*>(g_sim + (size_t)row0 * 4608 + colbase);
        d0[0] = make_float4(vlo[0], vlo[1], vlo[2], vlo[3]);
        d0[1] = make_float4(vlo[4], vlo[5], vlo[6], vlo[7]);
        float4* d1 = reinterpret_cast<float4*>(g_sim + (size_t)(row0 + 1) * 4608 + colbase);
        d1[0] = make_float4(vhi[0], vhi[1], vhi[2], vhi[3]);
        d1[1] = make_float4(vhi[4], vhi[5], vhi[6], vhi[7]);
    }
}

// ---------------- bitonic sort, 64 elements, descending ----------------
__device__ __forceinline__ void bitonic_desc64(float* arr, int t) {
#pragma unroll
    for (int sz = 2; sz <= 64; sz <<= 1) {
        for (int j = sz >> 1; j > 0; j >>= 1) {
            int ixj = t ^ j;
            if (ixj > t) {
                float a = arr[t], b = arr[ixj];
                bool sw = ((t & sz) == 0) ? (a < b) : (a > b);   // descending overall
                if (sw) { arr[t] = b; arr[ixj] = a; }
            }
            __syncthreads();
        }
    }
}

// ---------------- kernel 3: per-(c,i) postprocess ----------------
__global__ __launch_bounds__(64) void post_kernel(
    const float* __restrict__ w1_t2i, const float* __restrict__ b1_t2i,
    const float* __restrict__ w2_t2i, const float* __restrict__ b2_t2i,
    const float* __restrict__ w1_i2t, const float* __restrict__ b1_i2t,
    const float* __restrict__ w2_i2t, const float* __restrict__ b2_i2t,
    const int* __restrict__ cap_len, float* __restrict__ out)
{
    const int i = blockIdx.x;    // image
    const int c = blockIdx.y;    // caption
    const int t = threadIdx.x;   // 64 threads

    __shared__ float s[60][37];  // sim block, padded
    __shared__ float arr[64];
    __shared__ float inv[64];
    __shared__ float redbuf[2];
    __shared__ float meanv;
    __shared__ float hred[20];

    const float* simblk = g_sim + (size_t)(c * 60) * 4608 + i * 36;
    for (int idx = t; idx < 2160; idx += 64) {
        int w = idx / 36, r = idx - w * 36;
        s[w][r] = simblk[(size_t)w * 4608 + r];
    }
    const int L = cap_len[c];
    const int ns = (L > 20) ? L : 20;   // num_sel = max(cap_len, TOPK)
    __syncthreads();

    // =========== t2i path (normalize columns over selected words) ===========
    if (t < 36) {
        float ss = 0.f;
        for (int w = 0; w < ns; w++) { float v = s[w][t]; ss += v * v; }
        inv[t] = 1.0f / fmaxf(sqrtf(ss), EPSF);
    }
    __syncthreads();
    float rv = NEGF;
    if (t < ns) {                       // ns <= 60 < 64
        float m = -3.4e38f;
#pragma unroll 4
        for (int r = 0; r < 36; r++) m = fmaxf(m, s[t][r] * inv[r]);
        rv = m;
    }
    arr[t] = rv;
    __syncthreads();
    // row mean over w < cap_len
    float contrib = (t < L) ? arr[t] : 0.f;
#pragma unroll
    for (int o = 16; o > 0; o >>= 1) contrib += __shfl_xor_sync(0xffffffffu, contrib, o);
    if ((t & 31) == 0) redbuf[t >> 5] = contrib;
    __syncthreads();
    if (t == 0) meanv = (redbuf[0] + redbuf[1]) / (float)L;
    __syncthreads();
    float t2i_mean = meanv;
    __syncthreads();
    bitonic_desc64(arr, t);             // arr[0..19] = top-20 descending
    if (t < 20) {
        float h = b1_t2i[t];
#pragma unroll
        for (int k = 0; k < 20; k++) h = fmaf(arr[k], w1_t2i[k * 20 + t], h);
        h = fmaxf(h, 0.f);
        hred[t] = h * w2_t2i[t];
    }
    __syncthreads();
    if (t == 0) {
        float o = b2_t2i[0];
#pragma unroll
        for (int j = 0; j < 20; j++) o += hred[j];
        out[c * 128 + i] = o + t2i_mean;            // t2i_rel  (C, I)
        out[2 * 16384 + c * 128 + i] = t2i_mean;    // t2i_mean (C, I)
    }
    __syncthreads();

    // =========== i2t path (normalize rows over all 36 regions) ===========
    if (t < 60) {
        float ss = 0.f;
#pragma unroll 4
        for (int r = 0; r < 36; r++) { float v = s[t][r]; ss += v * v; }
        inv[t] = 1.0f / fmaxf(sqrtf(ss), EPSF);
    }
    __syncthreads();
    float cv = NEGF;
    if (t < 36) {
        float m = -3.4e38f;
        for (int w = 0; w < L; w++) m = fmaxf(m, s[w][t] * inv[w]);
        cv = m;
    }
    arr[t] = cv;
    __syncthreads();
    contrib = (t < 36) ? arr[t] : 0.f;
#pragma unroll
    for (int o = 16; o > 0; o >>= 1) contrib += __shfl_xor_sync(0xffffffffu, contrib, o);
    if ((t & 31) == 0) redbuf[t >> 5] = contrib;
    __syncthreads();
    if (t == 0) meanv = (redbuf[0] + redbuf[1]) * (1.0f / 36.0f);
    __syncthreads();
    float i2t_mean = meanv;
    __syncthreads();
    bitonic_desc64(arr, t);
    if (t < 20) {
        float h = b1_i2t[t];
#pragma unroll
        for (int k = 0; k < 20; k++) h = fmaf(arr[k], w1_i2t[k * 20 + t], h);
        h = fmaxf(h, 0.f);
        hred[t] = h * w2_i2t[t];
    }
    __syncthreads();
    if (t == 0) {
        float o = b2_i2t[0];
#pragma unroll
        for (int j = 0; j < 20; j++) o += hred[j];
        out[16384 + i * 128 + c] = o + i2t_mean;        // i2t_rel  (I, C)
        out[3 * 16384 + i * 128 + c] = i2t_mean;        // i2t_mean (I, C)
    }
}

// ---------------- launch ----------------
extern "C" void kernel_launch(void* const* d_in, const int* in_sizes, int n_in,
                              void* d_out, int out_size) {
    const float* img    = (const float*)d_in[0];
    const float* cap    = (const float*)d_in[1];
    const float* w1_t2i = (const float*)d_in[2];
    const float* b1_t2i = (const float*)d_in[3];
    const float* w2_t2i = (const float*)d_in[4];
    const float* b2_t2i = (const float*)d_in[5];
    const float* w1_i2t = (const float*)d_in[6];
    const float* b1_i2t = (const float*)d_in[7];
    const float* w2_i2t = (const float*)d_in[8];
    const float* b2_i2t = (const float*)d_in[9];
    const int*   cap_len = (const int*)d_in[10];
    float* out = (float*)d_out;

    nrm_kernel<<<12288, 256>>>(img, cap);
    gemm_kernel<<<dim3(36, 60), 256>>>();
    post_kernel<<<dim3(128, 128), 64>>>(w1_t2i, b1_t2i, w2_t2i, b2_t2i,
                                        w1_i2t, b1_i2t, w2_i2t, b2_i2t,
                                        cap_len, out);
}

// round 8
// speedup vs baseline: 2.0614x; 2.0614x over previous
#include <cuda_runtime.h>
#include <cuda_bf16.h>
#include <cstdint>

#define EPSF 1e-12f
#define NEGF -1e30f

// ---------------- static scratch (no runtime allocation allowed) ----------------
// split-bf16 normalized operands, row-major [row][1024]
__device__ __align__(256) __nv_bfloat16 g_cap_hi[7680 * 1024];
__device__ __align__(256) __nv_bfloat16 g_cap_lo[7680 * 1024];
__device__ __align__(256) __nv_bfloat16 g_img_hi[4608 * 1024];
__device__ __align__(256) __nv_bfloat16 g_img_lo[4608 * 1024];
__device__ __align__(256) float g_sim[7680 * 4608];   // leaky-relu applied

__device__ __forceinline__ uint32_t smem_u32(const void* p) {
    uint32_t a;
    asm("{ .reg .u64 t; cvta.to.shared.u64 t, %1; cvt.u32.u64 %0, t; }" : "=r"(a) : "l"(p));
    return a;
}
__device__ __forceinline__ void ldsm_x4(uint32_t* r, uint32_t addr) {
    asm volatile("ldmatrix.sync.aligned.m8n8.x4.shared.b16 {%0,%1,%2,%3}, [%4];"
                 : "=r"(r[0]), "=r"(r[1]), "=r"(r[2]), "=r"(r[3]) : "r"(addr));
}
__device__ __forceinline__ void mma16816(float* d, const uint32_t* a, const uint32_t* b) {
    asm volatile("mma.sync.aligned.m16n8k16.row.col.f32.bf16.bf16.f32 "
                 "{%0,%1,%2,%3}, {%4,%5,%6,%7}, {%8,%9}, {%0,%1,%2,%3};"
                 : "+f"(d[0]), "+f"(d[1]), "+f"(d[2]), "+f"(d[3])
                 : "r"(a[0]), "r"(a[1]), "r"(a[2]), "r"(a[3]), "r"(b[0]), "r"(b[1]));
}

// ---------------- kernel 1: L2 normalize + bf16 hi/lo split ----------------
__global__ __launch_bounds__(256) void nrm_kernel(const float* __restrict__ img,
                                                  const float* __restrict__ cap) {
    int row = blockIdx.x;
    const float4* src;
    __nv_bfloat16 *dh, *dl;
    if (row < 7680) {
        src = (const float4*)(cap + (size_t)row * 1024);
        dh = g_cap_hi + (size_t)row * 1024;
        dl = g_cap_lo + (size_t)row * 1024;
    } else {
        int r = row - 7680;
        src = (const float4*)(img + (size_t)r * 1024);
        dh = g_img_hi + (size_t)r * 1024;
        dl = g_img_lo + (size_t)r * 1024;
    }
    int t = threadIdx.x;
    float4 v = src[t];
    float ss = v.x * v.x + v.y * v.y + v.z * v.z + v.w * v.w;
#pragma unroll
    for (int o = 16; o > 0; o >>= 1) ss += __shfl_xor_sync(0xffffffffu, ss, o);
    __shared__ float red[8];
    if ((t & 31) == 0) red[t >> 5] = ss;
    __syncthreads();
    float tot = red[0] + red[1] + red[2] + red[3] + red[4] + red[5] + red[6] + red[7];
    float inv = 1.0f / fmaxf(sqrtf(tot), EPSF);
    float x[4] = {v.x * inv, v.y * inv, v.z * inv, v.w * inv};
    __nv_bfloat16 h[4], l[4];
#pragma unroll
    for (int j = 0; j < 4; j++) {
        h[j] = __float2bfloat16(x[j]);
        l[j] = __float2bfloat16(x[j] - __bfloat162float(h[j]));
    }
    __nv_bfloat162 h01(h[0], h[1]), h23(h[2], h[3]), l01(l[0], l[1]), l23(l[2], l[3]);
    uint2 uh, ul;
    uh.x = *reinterpret_cast<uint32_t*>(&h01); uh.y = *reinterpret_cast<uint32_t*>(&h23);
    ul.x = *reinterpret_cast<uint32_t*>(&l01); ul.y = *reinterpret_cast<uint32_t*>(&l23);
    *reinterpret_cast<uint2*>(dh + t * 4) = uh;
    *reinterpret_cast<uint2*>(dl + t * 4) = ul;
}

// ---------------- kernel 2: HMMA (mma.sync) GEMM, tile 128x128, K=1024 ----------------
// sim = cap_n . img_n^T via 3-term bf16 split, fp32 accumulate in registers.
// 8 warps, each computes 32(M) x 64(N); k-step 32 through 80B-pitch smem (ldmatrix-conflict-free).
__global__ __launch_bounds__(256) void gemm_mma_kernel() {
    // pitch 5 uint4 = 80B per 32-col row
    __shared__ __align__(16) uint4 sAh[128 * 5];
    __shared__ __align__(16) uint4 sAl[128 * 5];
    __shared__ __align__(16) uint4 sBh[128 * 5];
    __shared__ __align__(16) uint4 sBl[128 * 5];

    const int tid  = threadIdx.x;
    const int wid  = tid >> 5;
    const int lane = tid & 31;
    const int bx = blockIdx.x;   // 0..35  N tile (img)
    const int by = blockIdx.y;   // 0..59  M tile (cap)
    const int m_base = (wid & 3) * 32;   // warp M offset
    const int n_base = (wid >> 2) * 64;  // warp N offset

    const uint4* Ah = reinterpret_cast<const uint4*>(g_cap_hi) + (size_t)(by * 128) * 128;
    const uint4* Al = reinterpret_cast<const uint4*>(g_cap_lo) + (size_t)(by * 128) * 128;
    const uint4* Bh = reinterpret_cast<const uint4*>(g_img_hi) + (size_t)(bx * 128) * 128;
    const uint4* Bl = reinterpret_cast<const uint4*>(g_img_lo) + (size_t)(bx * 128) * 128;

    const uint32_t aAh = smem_u32(sAh), aAl = smem_u32(sAl);
    const uint32_t aBh = smem_u32(sBh), aBl = smem_u32(sBl);

    // precomputed ldmatrix lane addressing (byte offsets within the k32 stage)
    // A (m16k16, x4): row = lane&15, 16B-half = lane>>4
    const uint32_t a_row_off = (uint32_t)(lane & 15) * 80 + (uint32_t)(lane >> 4) * 16;
    // B (two n8 frags per x4): row = in4*16 + ((lane>>4)&1)*8 + (lane&7), 16B-half = (lane>>3)&1
    const uint32_t b_row_off = ((uint32_t)((lane >> 4) & 1) * 8 + (uint32_t)(lane & 7)) * 80 +
                               (uint32_t)((lane >> 3) & 1) * 16;

    float acc[2][8][4];
#pragma unroll
    for (int im = 0; im < 2; im++)
#pragma unroll
        for (int inf = 0; inf < 8; inf++)
#pragma unroll
            for (int q = 0; q < 4; q++) acc[im][inf][q] = 0.f;

#pragma unroll 1
    for (int kt = 0; kt < 32; kt++) {                 // 32 k-steps of 32
        const int kdiv8 = kt * 4;
        __syncthreads();                              // previous compute done before overwrite
#pragma unroll
        for (int h = 0; h < 2; h++) {                 // 512 16B-chunks per matrix / 256 thr
            int c = tid + h * 256;
            int row = c >> 2, j = c & 3;
            size_t g = (size_t)row * 128 + kdiv8 + j;
            int s = row * 5 + j;
            sAh[s] = Ah[g];
            sAl[s] = Al[g];
            sBh[s] = Bh[g];
            sBl[s] = Bl[g];
        }
        __syncthreads();

#pragma unroll
        for (int k16 = 0; k16 < 2; k16++) {
            const uint32_t kb = k16 * 32;             // 16 bf16 = 32 bytes
            uint32_t ah[2][4], al[2][4], bh[8][2], bl[8][2];
#pragma unroll
            for (int im = 0; im < 2; im++) {
                uint32_t ro = (uint32_t)(m_base + im * 16) * 80 + a_row_off + kb;
                ldsm_x4(ah[im], aAh + ro);
                ldsm_x4(al[im], aAl + ro);
            }
#pragma unroll
            for (int in4 = 0; in4 < 4; in4++) {
                uint32_t ro = (uint32_t)(n_base + in4 * 16) * 80 + b_row_off + kb;
                uint32_t r[4];
                ldsm_x4(r, aBh + ro);
                bh[2 * in4][0] = r[0]; bh[2 * in4][1] = r[1];
                bh[2 * in4 + 1][0] = r[2]; bh[2 * in4 + 1][1] = r[3];
                ldsm_x4(r, aBl + ro);
                bl[2 * in4][0] = r[0]; bl[2 * in4][1] = r[1];
                bl[2 * in4 + 1][0] = r[2]; bl[2 * in4 + 1][1] = r[3];
            }
#pragma unroll
            for (int im = 0; im < 2; im++)
#pragma unroll
                for (int inf = 0; inf < 8; inf++) {
                    mma16816(acc[im][inf], ah[im], bh[inf]);   // hi*hi
                    mma16816(acc[im][inf], ah[im], bl[inf]);   // hi*lo
                    mma16816(acc[im][inf], al[im], bh[inf]);   // lo*hi
                }
        }
    }

    // epilogue: leaky relu + store (c-frag: rows lane>>2 / +8, cols (lane&3)*2)
    const int r0 = by * 128 + m_base + (lane >> 2);
    const int c0 = bx * 128 + n_base + (lane & 3) * 2;
#pragma unroll
    for (int im = 0; im < 2; im++)
#pragma unroll
        for (int inf = 0; inf < 8; inf++) {
            float* a4 = acc[im][inf];
            int row = r0 + im * 16;
            int col = c0 + inf * 8;
            float2 v0, v1;
            v0.x = (a4[0] >= 0.f) ? a4[0] : 0.1f * a4[0];
            v0.y = (a4[1] >= 0.f) ? a4[1] : 0.1f * a4[1];
            v1.x = (a4[2] >= 0.f) ? a4[2] : 0.1f * a4[2];
            v1.y = (a4[3] >= 0.f) ? a4[3] : 0.1f * a4[3];
            *reinterpret_cast<float2*>(g_sim + (size_t)row * 4608 + col) = v0;
            *reinterpret_cast<float2*>(g_sim + (size_t)(row + 8) * 4608 + col) = v1;
        }
}

// ---------------- bitonic sort, 64 elements, descending ----------------
__device__ __forceinline__ void bitonic_desc64(float* arr, int t) {
#pragma unroll
    for (int sz = 2; sz <= 64; sz <<= 1) {
        for (int j = sz >> 1; j > 0; j >>= 1) {
            int ixj = t ^ j;
            if (ixj > t) {
                float a = arr[t], b = arr[ixj];
                bool sw = ((t & sz) == 0) ? (a < b) : (a > b);
                if (sw) { arr[t] = b; arr[ixj] = a; }
            }
            __syncthreads();
        }
    }
}

// ---------------- kernel 3: per-(c,i) postprocess ----------------
__global__ __launch_bounds__(64) void post_kernel(
    const float* __restrict__ w1_t2i, const float* __restrict__ b1_t2i,
    const float* __restrict__ w2_t2i, const float* __restrict__ b2_t2i,
    const float* __restrict__ w1_i2t, const float* __restrict__ b1_i2t,
    const float* __restrict__ w2_i2t, const float* __restrict__ b2_i2t,
    const int* __restrict__ cap_len, float* __restrict__ out)
{
    const int i = blockIdx.x;    // image
    const int c = blockIdx.y;    // caption
    const int t = threadIdx.x;   // 64 threads

    __shared__ float s[60][37];
    __shared__ float arr[64];
    __shared__ float inv[64];
    __shared__ float redbuf[2];
    __shared__ float meanv;
    __shared__ float hred[20];

    const float* simblk = g_sim + (size_t)(c * 60) * 4608 + i * 36;
    for (int idx = t; idx < 2160; idx += 64) {
        int w = idx / 36, r = idx - w * 36;
        s[w][r] = simblk[(size_t)w * 4608 + r];
    }
    const int L = cap_len[c];
    const int ns = (L > 20) ? L : 20;
    __syncthreads();

    // ===== t2i =====
    if (t < 36) {
        float ss = 0.f;
        for (int w = 0; w < ns; w++) { float v = s[w][t]; ss += v * v; }
        inv[t] = 1.0f / fmaxf(sqrtf(ss), EPSF);
    }
    __syncthreads();
    float rv = NEGF;
    if (t < ns) {
        float m = -3.4e38f;
#pragma unroll 4
        for (int r = 0; r < 36; r++) m = fmaxf(m, s[t][r] * inv[r]);
        rv = m;
    }
    arr[t] = rv;
    __syncthreads();
    float contrib = (t < L) ? arr[t] : 0.f;
#pragma unroll
    for (int o = 16; o > 0; o >>= 1) contrib += __shfl_xor_sync(0xffffffffu, contrib, o);
    if ((t & 31) == 0) redbuf[t >> 5] = contrib;
    __syncthreads();
    if (t == 0) meanv = (redbuf[0] + redbuf[1]) / (float)L;
    __syncthreads();
    float t2i_mean = meanv;
    __syncthreads();
    bitonic_desc64(arr, t);
    if (t < 20) {
        float h = b1_t2i[t];
#pragma unroll
        for (int k = 0; k < 20; k++) h = fmaf(arr[k], w1_t2i[k * 20 + t], h);
        h = fmaxf(h, 0.f);
        hred[t] = h * w2_t2i[t];
    }
    __syncthreads();
    if (t == 0) {
        float o = b2_t2i[0];
#pragma unroll
        for (int j = 0; j < 20; j++) o += hred[j];
        out[c * 128 + i] = o + t2i_mean;
        out[2 * 16384 + c * 128 + i] = t2i_mean;
    }
    __syncthreads();

    // ===== i2t =====
    if (t < 60) {
        float ss = 0.f;
#pragma unroll 4
        for (int r = 0; r < 36; r++) { float v = s[t][r]; ss += v * v; }
        inv[t] = 1.0f / fmaxf(sqrtf(ss), EPSF);
    }
    __syncthreads();
    float cv = NEGF;
    if (t < 36) {
        float m = -3.4e38f;
        for (int w = 0; w < L; w++) m = fmaxf(m, s[w][t] * inv[w]);
        cv = m;
    }
    arr[t] = cv;
    __syncthreads();
    contrib = (t < 36) ? arr[t] : 0.f;
#pragma unroll
    for (int o = 16; o > 0; o >>= 1) contrib += __shfl_xor_sync(0xffffffffu, contrib, o);
    if ((t & 31) == 0) redbuf[t >> 5] = contrib;
    __syncthreads();
    if (t == 0) meanv = (redbuf[0] + redbuf[1]) * (1.0f / 36.0f);
    __syncthreads();
    float i2t_mean = meanv;
    __syncthreads();
    bitonic_desc64(arr, t);
    if (t < 20) {
        float h = b1_i2t[t];
#pragma unroll
        for (int k = 0; k < 20; k++) h = fmaf(arr[k], w1_i2t[k * 20 + t], h);
        h = fmaxf(h, 0.f);
        hred[t] = h * w2_i2t[t];
    }
    __syncthreads();
    if (t == 0) {
        float o = b2_i2t[0];
#pragma unroll
        for (int j = 0; j < 20; j++) o += hred[j];
        out[16384 + i * 128 + c] = o + i2t_mean;
        out[3 * 16384 + i * 128 + c] = i2t_mean;
    }
}

// ---------------- launch ----------------
extern "C" void kernel_launch(void* const* d_in, const int* in_sizes, int n_in,
                              void* d_out, int out_size) {
    const float* img    = (const float*)d_in[0];
    const float* cap    = (const float*)d_in[1];
    const float* w1_t2i = (const float*)d_in[2];
    const float* b1_t2i = (const float*)d_in[3];
    const float* w2_t2i = (const float*)d_in[4];
    const float* b2_t2i = (const float*)d_in[5];
    const float* w1_i2t = (const float*)d_in[6];
    const float* b1_i2t = (const float*)d_in[7];
    const float* w2_i2t = (const float*)d_in[8];
    const float* b2_i2t = (const float*)d_in[9];
    const int*   cap_len = (const int*)d_in[10];
    float* out = (float*)d_out;

    nrm_kernel<<<12288, 256>>>(img, cap);
    gemm_mma_kernel<<<dim3(36, 60), 256>>>();
    post_kernel<<<dim3(128, 128), 64>>>(w1_t2i, b1_t2i, w2_t2i, b2_t2i,
                                        w1_i2t, b1_i2t, w2_i2t, b2_i2t,
                                        cap_len, out);
}